// round 1
// baseline (speedup 1.0000x reference)
#include <cuda_runtime.h>
#include <cstdint>
#include <cstdio>

// Problem constants
#define T_STEPS 512
#define BATCH   256
#define DIN     128
#define HID     512
#define KTOT    640          // DIN + HID

// Tiling
#define P_B 8                // batch groups
#define P_N 16               // n-slices per group
#define B_TILE 32            // batch rows per CTA (M)
#define N_SLICE 32           // H columns per CTA
#define NC 64                // combined N (Wc slice | Wt slice)
#define KC 128               // K chunk staged in smem
#define NCHUNK 5             // 640 / 128
#define NTHREADS 256
#define GRID (P_B * P_N)

// Shared memory layout (in uint32 units)
#define OFF_W   0            // 80 kg * 64 cc * 8 = 40960 (tf32 weights, fragment-permuted)
#define OFF_Z   40960        // 2 * 16 kg * 32 m * 8 = 8192 (z chunks, double buffered)
#define OFF_EPI 49152        // 32 * 66 floats = 2112
#define OFF_BC  51264        // 32
#define OFF_BT  51296        // 32
#define OFF_WO  51328        // 512
#define SMEM_U32 51840
#define SMEM_BYTES (SMEM_U32 * 4)   // 207360 B

// Persistent device state
__device__ float    g_h[2][BATCH][HID];       // double-buffered hidden state (fp32)
__device__ unsigned g_count[P_B];             // barrier counters (zero-init)
__device__ volatile unsigned g_sense[P_B];    // barrier sense (zero-init; 512 toggles/launch -> returns to 0)

__device__ __forceinline__ unsigned f2tf(float f) {
    unsigned u;
    asm("cvt.rna.tf32.f32 %0, %1;" : "=r"(u) : "f"(f));
    return u;
}

__device__ __forceinline__ void mma_tf32(float* c,
                                         unsigned a0, unsigned a1, unsigned a2, unsigned a3,
                                         unsigned b0, unsigned b1) {
    asm("mma.sync.aligned.m16n8k8.row.col.f32.tf32.tf32.f32 "
        "{%0,%1,%2,%3},{%4,%5,%6,%7},{%8,%9},{%0,%1,%2,%3};"
        : "+f"(c[0]), "+f"(c[1]), "+f"(c[2]), "+f"(c[3])
        : "r"(a0), "r"(a1), "r"(a2), "r"(a3), "r"(b0), "r"(b1));
}

// Stage one K-chunk of z = [x_t | h] into smem as tf32 in mma-fragment-permuted
// layout: dst[((k_local>>3)*32 + m)*8 + ((k&3)*2 + ((k>>2)&1))]
__device__ __forceinline__ void stage_chunk(unsigned* dst, const float* __restrict__ x_seq,
                                            int s, int c, int p, int b0, int tid) {
    const float* src;
    int stride;
    if (c == 0) { src = x_seq + ((size_t)s * BATCH + b0) * DIN; stride = DIN; }
    else        { src = &g_h[p][b0][0] + (c - 1) * KC;           stride = HID; }
    const bool zero = (s == 0 && c > 0);   // h0 = 0
#pragma unroll
    for (int i = 0; i < 4; i++) {
        int f  = i * NTHREADS + tid;       // 0..1023 float4s
        int m  = f >> 5;                   // row 0..31
        int k4 = (f & 31) * 4;             // 0..124
        float4 v = make_float4(0.f, 0.f, 0.f, 0.f);
        if (!zero) v = *(const float4*)(src + (size_t)m * stride + k4);
        unsigned* d = dst + (((k4 >> 3) * 32 + m) * 8 + ((k4 >> 2) & 1));
        d[0] = f2tf(v.x); d[2] = f2tf(v.y); d[4] = f2tf(v.z); d[6] = f2tf(v.w);
    }
}

__global__ void __launch_bounds__(NTHREADS, 1)
liquid_kernel(const float* __restrict__ x_seq,
              const float* __restrict__ Wc, const float* __restrict__ bc,
              const float* __restrict__ Wt, const float* __restrict__ bt,
              const float* __restrict__ Wo, const float* __restrict__ bo,
              float* __restrict__ out) {
    extern __shared__ unsigned smem[];
    unsigned* sW  = smem + OFF_W;
    unsigned* sZ  = smem + OFF_Z;
    float*    sEpi = (float*)(smem + OFF_EPI);
    float*    sBc  = (float*)(smem + OFF_BC);
    float*    sBt  = (float*)(smem + OFF_BT);
    float*    sWo  = (float*)(smem + OFF_WO);

    const int tid  = threadIdx.x;
    const int gb   = blockIdx.x / P_N;   // batch group 0..7
    const int jn   = blockIdx.x % P_N;   // n-slice     0..15
    const int b0   = gb * B_TILE;
    const int n0   = jn * N_SLICE;
    const int lane = tid & 31;
    const int wid  = tid >> 5;
    const int wm   = wid & 1;            // M warp (16 rows)
    const int wn   = wid >> 1;           // N warp (16 combined cols)

    // ---- init: weights -> smem (tf32, fragment-permuted [kg][cc][pk]) ----
    for (int e = tid; e < KTOT * NC; e += NTHREADS) {
        int k = e >> 6, cc = e & 63;
        float w = (cc < N_SLICE) ? Wc[k * HID + n0 + cc]
                                 : Wt[k * HID + n0 + (cc - N_SLICE)];
        sW[((k >> 3) * 64 + cc) * 8 + ((k & 3) * 2) + ((k >> 2) & 1)] = f2tf(w);
    }
    if (tid < N_SLICE) { sBc[tid] = bc[n0 + tid]; sBt[tid] = bt[n0 + tid]; }
    if (jn == 0) for (int e = tid; e < HID; e += NTHREADS) sWo[e] = Wo[e];
    const float bo_v = bo[0];
    __syncthreads();

    unsigned lsense = 0;

    for (int s = 0; s < T_STEPS; s++) {
        const int p = s & 1;

        // ---- y output for previous step (h state of step s lives in g_h[p]) ----
        if (jn == 0 && s > 0) {
#pragma unroll
            for (int rr = 0; rr < 4; rr++) {
                int b = wid * 4 + rr;
                const float* hr = &g_h[p][b0 + b][0];
                float acc = 0.f;
#pragma unroll
                for (int j = 0; j < HID / 32; j++)
                    acc += hr[lane + j * 32] * sWo[lane + j * 32];
#pragma unroll
                for (int o = 16; o; o >>= 1) acc += __shfl_xor_sync(0xffffffffu, acc, o);
                if (lane == 0) out[(size_t)(s - 1) * BATCH + b0 + b] = acc + bo_v;
            }
        }

        // ---- GEMM: out[32 x 64] = z[32 x 640] @ [Wc|Wt][640 x 64] ----
        float acc0[4] = {0.f, 0.f, 0.f, 0.f};
        float acc1[4] = {0.f, 0.f, 0.f, 0.f};

        stage_chunk(sZ, x_seq, s, 0, p, b0, tid);
        __syncthreads();

        for (int c = 0; c < NCHUNK; c++) {
            if (c + 1 < NCHUNK)
                stage_chunk(sZ + ((c + 1) & 1) * 4096, x_seq, s, c + 1, p, b0, tid);

            const unsigned* zb = sZ + (c & 1) * 4096;
            const unsigned* wb = sW + (c * 16) * 512;
#pragma unroll
            for (int kg = 0; kg < 16; kg++) {
                const unsigned* z = zb + kg * 256;
                uint2 a01 = *(const uint2*)(z + (wm * 16 + (lane >> 2)) * 8 + (lane & 3) * 2);
                uint2 a23 = *(const uint2*)(z + (wm * 16 + 8 + (lane >> 2)) * 8 + (lane & 3) * 2);
                const unsigned* w = wb + kg * 512;
                uint2 bA = *(const uint2*)(w + (wn * 16 + (lane >> 2)) * 8 + (lane & 3) * 2);
                uint2 bB = *(const uint2*)(w + (wn * 16 + 8 + (lane >> 2)) * 8 + (lane & 3) * 2);
                // a0=(r,k) a1=(r+8,k) a2=(r,k+4) a3=(r+8,k+4); b0=(k,n) b1=(k+4,n)
                mma_tf32(acc0, a01.x, a23.x, a01.y, a23.y, bA.x, bA.y);
                mma_tf32(acc1, a01.x, a23.x, a01.y, a23.y, bB.x, bB.y);
            }
            __syncthreads();
        }

        // ---- scatter accumulators to smem epilogue buffer [32][66] ----
        {
            int row  = wm * 16 + (lane >> 2);
            int colb = wn * 16 + (lane & 3) * 2;
            *(float2*)&sEpi[row * 66 + colb]            = make_float2(acc0[0], acc0[1]);
            *(float2*)&sEpi[(row + 8) * 66 + colb]      = make_float2(acc0[2], acc0[3]);
            *(float2*)&sEpi[row * 66 + colb + 8]        = make_float2(acc1[0], acc1[1]);
            *(float2*)&sEpi[(row + 8) * 66 + colb + 8]  = make_float2(acc1[2], acc1[3]);
        }
        __syncthreads();

        // ---- elementwise: tanh / sigmoid / ODE Euler update, write tau + h_next ----
#pragma unroll
        for (int i = 0; i < 4; i++) {
            int e  = i * NTHREADS + tid;   // 0..1023
            int b  = e >> 5;               // local batch row
            int nl = e & 31;               // local column
            float uc   = sEpi[b * 66 + nl]      + sBc[nl];
            float ut   = sEpi[b * 66 + nl + 32] + sBt[nl];
            float cand = tanhf(uc);
            float sig  = 1.f / (1.f + expf(-ut));
            float tau  = 0.2f + 1.8f * sig;
            float h    = (s == 0) ? 0.f : g_h[p][b0 + b][n0 + nl];
            float hn   = h + 0.1f * (cand - h) / tau;
            g_h[p ^ 1][b0 + b][n0 + nl] = hn;
            out[(size_t)T_STEPS * BATCH +
                ((size_t)s * BATCH + b0 + b) * HID + n0 + nl] = tau;
        }

        // ---- per-group sense-reversing barrier (16 CTAs) ----
        __threadfence();
        __syncthreads();
        if (tid == 0) {
            unsigned my = lsense ^ 1u;
            lsense = my;
            unsigned old = atomicAdd(&g_count[gb], 1u);
            if (old == P_N - 1u) {
                g_count[gb] = 0u;
                __threadfence();
                g_sense[gb] = my;
            } else {
                while (g_sense[gb] != my) { }
                __threadfence();
            }
        }
        __syncthreads();
    }

    // ---- y for the final step (h_512 lives in g_h[0]) ----
    if (jn == 0) {
#pragma unroll
        for (int rr = 0; rr < 4; rr++) {
            int b = wid * 4 + rr;
            const float* hr = &g_h[0][b0 + b][0];
            float acc = 0.f;
#pragma unroll
            for (int j = 0; j < HID / 32; j++)
                acc += hr[lane + j * 32] * sWo[lane + j * 32];
#pragma unroll
            for (int o = 16; o; o >>= 1) acc += __shfl_xor_sync(0xffffffffu, acc, o);
            if (lane == 0) out[(size_t)(T_STEPS - 1) * BATCH + b0 + b] = acc + bo_v;
        }
    }
}

extern "C" void kernel_launch(void* const* d_in, const int* in_sizes, int n_in,
                              void* d_out, int out_size) {
    (void)in_sizes; (void)n_in; (void)out_size;
    const float* x_seq = (const float*)d_in[0];
    const float* Wc    = (const float*)d_in[1];
    const float* bc    = (const float*)d_in[2];
    const float* Wt    = (const float*)d_in[3];
    const float* bt    = (const float*)d_in[4];
    const float* Wo    = (const float*)d_in[5];
    const float* bo    = (const float*)d_in[6];
    float* out = (float*)d_out;

    cudaFuncSetAttribute(liquid_kernel, cudaFuncAttributeMaxDynamicSharedMemorySize, SMEM_BYTES);
    liquid_kernel<<<GRID, NTHREADS, SMEM_BYTES>>>(x_seq, Wc, bc, Wt, bt, Wo, bo, out);
}

// round 2
// speedup vs baseline: 1.8599x; 1.8599x over previous
#include <cuda_runtime.h>
#include <cstdint>

// Problem constants
#define T_STEPS 512
#define BATCH   256
#define DIN     128
#define HID     512
#define KTOT    640          // DIN + HID

// Tiling
#define P_B 8                // batch groups
#define P_N 16               // n-slices per group
#define B_TILE 32            // batch rows per CTA (M)
#define N_SLICE 32           // H columns per CTA
#define NC 64                // combined N (Wc slice | Wt slice)
#define KC 128               // K chunk staged in smem
#define NCHUNK 5             // 640 / 128
#define NTHREADS 512
#define GRID (P_B * P_N)

// Shared memory layout (uint32 units)
#define OFF_W   0            // 80 kg * 64 cc * 8 = 40960 (tf32 weights, swizzled frag layout)
#define OFF_Z   40960        // 2 * 16 kg * 32 m * 8 = 8192 (z chunks, double buffered)
#define OFF_EPI 49152        // 4 wk-buffers * 32 * 66 = 8448
#define OFF_BC  57600        // 32
#define OFF_BT  57632        // 32
#define SMEM_U32 57664
#define SMEM_BYTES (SMEM_U32 * 4)   // 230656 B  (< 232448 limit)

// Persistent device state
__device__ float    g_h[2][BATCH][HID];       // double-buffered hidden state
__device__ float    g_ypart[2][BATCH][P_N];   // per-slice y partial sums, double buffered
__device__ unsigned g_count[P_B];             // barrier counters
__device__ volatile unsigned g_sense[P_B];    // barrier sense (even #toggles per launch)

__device__ __forceinline__ unsigned f2tf(float f) {
    unsigned u;
    asm("cvt.rna.tf32.f32 %0, %1;" : "=r"(u) : "f"(f));
    return u;
}

// XOR swizzle on word-address bits [1:4], keyed by k-group. Keeps uint2 pairing
// (bit0 untouched); spreads both STS scatter and frag LDS across all 32 banks.
__device__ __forceinline__ int swz(int addr, int kg) {
    return addr ^ ((kg & 3) << 3) ^ (((kg >> 2) & 3) << 1);
}

__device__ __forceinline__ void mma_tf32(float* c,
                                         unsigned a0, unsigned a1, unsigned a2, unsigned a3,
                                         unsigned b0, unsigned b1) {
    asm("mma.sync.aligned.m16n8k8.row.col.f32.tf32.tf32.f32 "
        "{%0,%1,%2,%3},{%4,%5,%6,%7},{%8,%9},{%0,%1,%2,%3};"
        : "+f"(c[0]), "+f"(c[1]), "+f"(c[2]), "+f"(c[3])
        : "r"(a0), "r"(a1), "r"(a2), "r"(a3), "r"(b0), "r"(b1));
}

// Load one K-chunk of z = [x_t | h] into registers (2 float4 per thread).
__device__ __forceinline__ void ld_chunk(float4* v, const float* __restrict__ x_seq,
                                         int s, int c, int p, int b0, int tid) {
    if (s == 0 && c > 0) {   // h0 = 0
        v[0] = make_float4(0.f, 0.f, 0.f, 0.f);
        v[1] = v[0];
        return;
    }
    const float* src;
    int stride;
    if (c == 0) { src = x_seq + ((size_t)s * BATCH + b0) * DIN; stride = DIN; }
    else        { src = &g_h[p][b0][0] + (c - 1) * KC;           stride = HID; }
#pragma unroll
    for (int i = 0; i < 2; i++) {
        int f  = i * NTHREADS + tid;   // 0..1023 float4s
        int m  = f >> 5;               // row 0..31
        int k4 = (f & 31) * 4;         // 0..124
        v[i] = *(const float4*)(src + (size_t)m * stride + k4);
    }
}

// Store the prefetched chunk into smem (tf32, swizzled fragment layout).
__device__ __forceinline__ void st_chunk(const float4* v, unsigned* dst, int tid) {
#pragma unroll
    for (int i = 0; i < 2; i++) {
        int f  = i * NTHREADS + tid;
        int m  = f >> 5;
        int k4 = (f & 31) * 4;
        int kg = k4 >> 3;
        int a0 = (kg * 32 + m) * 8 + ((k4 >> 2) & 1);
        dst[swz(a0 + 0, kg)] = f2tf(v[i].x);
        dst[swz(a0 + 2, kg)] = f2tf(v[i].y);
        dst[swz(a0 + 4, kg)] = f2tf(v[i].z);
        dst[swz(a0 + 6, kg)] = f2tf(v[i].w);
    }
}

__global__ void __launch_bounds__(NTHREADS, 1)
liquid_kernel(const float* __restrict__ x_seq,
              const float* __restrict__ Wc, const float* __restrict__ bc,
              const float* __restrict__ Wt, const float* __restrict__ bt,
              const float* __restrict__ Wo, const float* __restrict__ bo,
              float* __restrict__ out) {
    extern __shared__ unsigned smem[];
    unsigned* sW   = smem + OFF_W;
    unsigned* sZ   = smem + OFF_Z;
    float*    sEpi = (float*)(smem + OFF_EPI);
    float*    sBc  = (float*)(smem + OFF_BC);
    float*    sBt  = (float*)(smem + OFF_BT);

    const int tid  = threadIdx.x;
    const int gb   = blockIdx.x / P_N;   // batch group 0..7
    const int jn   = blockIdx.x % P_N;   // n-slice     0..15
    const int b0   = gb * B_TILE;
    const int n0   = jn * N_SLICE;
    const int lane = tid & 31;
    const int wid  = tid >> 5;           // 0..15
    const int wm   = wid & 1;            // M half (16 rows)
    const int wn   = (wid >> 1) & 1;     // N half (32 combined cols)
    const int wk   = wid >> 2;           // K quarter (4 kg per chunk)

    // ---- init: weights -> smem (tf32, swizzled fragment layout) ----
    for (int e = tid; e < KTOT * NC; e += NTHREADS) {
        int k = e >> 6, cc = e & 63;
        float w = (cc < N_SLICE) ? Wc[k * HID + n0 + cc]
                                 : Wt[k * HID + n0 + (cc - N_SLICE)];
        int kgg = k >> 3;
        int idx = (kgg * 64 + cc) * 8 + ((k & 3) * 2) + ((k >> 2) & 1);
        sW[swz(idx, kgg)] = f2tf(w);
    }
    if (tid < N_SLICE) { sBc[tid] = bc[n0 + tid]; sBt[tid] = bt[n0 + tid]; }
    const float wo_v = Wo[n0 + (tid & 31)];
    const float bo_v = bo[0];
    __syncthreads();

    unsigned lsense = 0;

    for (int s = 0; s < T_STEPS; s++) {
        const int p = s & 1;

        // ---- finish y for previous step: sum 16 slice-partials (warp 0) ----
        if (s > 0 && tid < 32) {
            int r = tid >> 4, j = tid & 15;
            int b = b0 + jn * 2 + r;
            float v = g_ypart[(s & 1) ^ 1][b][j];
#pragma unroll
            for (int o = 8; o; o >>= 1) v += __shfl_xor_sync(0xffffffffu, v, o);
            if (j == 0) out[(size_t)(s - 1) * BATCH + b] = v + bo_v;
        }

        // ---- GEMM: [32 x 64] = z[32 x 640] @ [Wc|Wt][640 x 64], K split 4-way ----
        float acc[4][4] = {};
        float4 vNext[2];

        ld_chunk(vNext, x_seq, s, 0, p, b0, tid);
        st_chunk(vNext, sZ, tid);
        __syncthreads();

        for (int c = 0; c < NCHUNK; c++) {
            if (c + 1 < NCHUNK) ld_chunk(vNext, x_seq, s, c + 1, p, b0, tid);

            const unsigned* zb = sZ + (c & 1) * 4096;
#pragma unroll
            for (int i = 0; i < 4; i++) {
                int kg  = wk * 4 + i;                 // kg within chunk (0..15)
                int kgg = c * 16 + kg;                // global kg (0..79)
                int ab  = (kg * 32 + wm * 16 + (lane >> 2)) * 8 + (lane & 3) * 2;
                uint2 a01 = *(const uint2*)(zb + swz(ab, kg));
                uint2 a23 = *(const uint2*)(zb + swz(ab + 64, kg));
                const unsigned* w = sW + kgg * 512;
#pragma unroll
                for (int t = 0; t < 4; t++) {
                    int bb = (wn * 32 + t * 8 + (lane >> 2)) * 8 + (lane & 3) * 2;
                    uint2 b01 = *(const uint2*)(w + swz(bb, kgg));
                    mma_tf32(acc[t], a01.x, a23.x, a01.y, a23.y, b01.x, b01.y);
                }
            }

            if (c + 1 < NCHUNK) st_chunk(vNext, sZ + ((c + 1) & 1) * 4096, tid);
            __syncthreads();
        }

        // ---- scatter partial accumulators to per-wk epilogue buffers ----
        {
            float* eb = sEpi + wk * 2112;
            int row = wm * 16 + (lane >> 2);
#pragma unroll
            for (int t = 0; t < 4; t++) {
                int col = wn * 32 + t * 8 + (lane & 3) * 2;
                *(float2*)&eb[row * 66 + col]       = make_float2(acc[t][0], acc[t][1]);
                *(float2*)&eb[(row + 8) * 66 + col] = make_float2(acc[t][2], acc[t][3]);
            }
        }
        __syncthreads();

        // ---- elementwise: reduce wk partials, tanh/sigmoid/Euler, y-partials ----
#pragma unroll
        for (int i = 0; i < 2; i++) {
            int e  = i * NTHREADS + tid;   // 0..1023
            int b  = e >> 5;
            int nl = e & 31;               // == lane
            float uc = sBc[nl], ut = sBt[nl];
#pragma unroll
            for (int q = 0; q < 4; q++) {
                uc += sEpi[q * 2112 + b * 66 + nl];
                ut += sEpi[q * 2112 + b * 66 + nl + 32];
            }
            float ea   = __expf(-2.f * fabsf(uc));
            float cand = copysignf(__fdividef(1.f - ea, 1.f + ea), uc);
            float sg   = __fdividef(1.f, 1.f + __expf(-ut));
            float tau  = 0.2f + 1.8f * sg;
            float h    = (s == 0) ? 0.f : g_h[p][b0 + b][n0 + nl];
            float hn   = h + 0.1f * __fdividef(cand - h, tau);
            g_h[p ^ 1][b0 + b][n0 + nl] = hn;
            out[(size_t)T_STEPS * BATCH +
                ((size_t)s * BATCH + b0 + b) * HID + n0 + nl] = tau;

            float pp = hn * wo_v;
#pragma unroll
            for (int o = 16; o; o >>= 1) pp += __shfl_xor_sync(0xffffffffu, pp, o);
            if (lane == 0) g_ypart[s & 1][b0 + b][jn] = pp;
        }

        // ---- per-group sense-reversing barrier (16 CTAs) ----
        __threadfence();
        __syncthreads();
        if (tid == 0) {
            unsigned my = lsense ^ 1u;
            lsense = my;
            unsigned old = atomicAdd(&g_count[gb], 1u);
            if (old == P_N - 1u) {
                g_count[gb] = 0u;
                __threadfence();
                g_sense[gb] = my;
            } else {
                while (g_sense[gb] != my) { }
                __threadfence();
            }
        }
        __syncthreads();
    }

    // ---- y for the final step ----
    if (tid < 32) {
        int r = tid >> 4, j = tid & 15;
        int b = b0 + jn * 2 + r;
        float v = g_ypart[(T_STEPS & 1) ^ 1][b][j];
#pragma unroll
        for (int o = 8; o; o >>= 1) v += __shfl_xor_sync(0xffffffffu, v, o);
        if (j == 0) out[(size_t)(T_STEPS - 1) * BATCH + b] = v + bo_v;
    }
}

extern "C" void kernel_launch(void* const* d_in, const int* in_sizes, int n_in,
                              void* d_out, int out_size) {
    (void)in_sizes; (void)n_in; (void)out_size;
    const float* x_seq = (const float*)d_in[0];
    const float* Wc    = (const float*)d_in[1];
    const float* bc    = (const float*)d_in[2];
    const float* Wt    = (const float*)d_in[3];
    const float* bt    = (const float*)d_in[4];
    const float* Wo    = (const float*)d_in[5];
    const float* bo    = (const float*)d_in[6];
    float* out = (float*)d_out;

    cudaFuncSetAttribute(liquid_kernel, cudaFuncAttributeMaxDynamicSharedMemorySize, SMEM_BYTES);
    liquid_kernel<<<GRID, NTHREADS, SMEM_BYTES>>>(x_seq, Wc, bc, Wt, bt, Wo, bo, out);
}

// round 4
// speedup vs baseline: 2.3729x; 1.2758x over previous
#include <cuda_runtime.h>
#include <cuda_fp16.h>
#include <cstdint>

// Problem constants
#define T_STEPS 512
#define BATCH   256
#define DIN     128
#define HID     512
#define KTOT    640          // DIN + HID

// Tiling
#define P_B 8                // batch groups
#define P_N 16               // n-slices per group
#define B_TILE 32            // batch rows per CTA (M)
#define N_SLICE 32           // H columns per CTA
#define NC 64                // combined N (Wc | Wt)
#define KC 128               // K chunk staged in smem (halves)
#define NCHUNK 5             // 640 / 128
#define NKG 8                // kg16 groups per chunk
#define KGG_TOT 40           // 640 / 16
#define NTHREADS 512
#define GRID (P_B * P_N)

// Shared memory layout (uint32 units)
#define OFF_WF  0            // B frag layout: 40 kg * 4 ntp * 32 lane * 4 = 20480 u32 (80KB)
#define OFF_Z   20480        // 2 buffers * 2048 u32 (each 32 rows x 128 halves = 8KB)
#define OFF_EPI 24576        // 4 wk-buffers * 32*66 = 8448
#define OFF_BC  33024        // 32
#define OFF_BT  33056        // 32
#define SMEM_U32 33088
#define SMEM_BYTES (SMEM_U32 * 4)   // 132352 B

#define ZBUF_BYTES 8192

// Persistent device state
__device__ float    g_h[2][BATCH][HID];
__device__ float    g_ypart[2][BATCH][P_N];
__device__ unsigned g_count[P_B];
__device__ volatile unsigned g_sense[P_B];

__device__ __forceinline__ void mma_f16(float* c, unsigned a0, unsigned a1,
                                        unsigned a2, unsigned a3,
                                        unsigned b0, unsigned b1) {
    asm("mma.sync.aligned.m16n8k16.row.col.f32.f16.f16.f32 "
        "{%0,%1,%2,%3},{%4,%5,%6,%7},{%8,%9},{%0,%1,%2,%3};"
        : "+f"(c[0]), "+f"(c[1]), "+f"(c[2]), "+f"(c[3])
        : "r"(a0), "r"(a1), "r"(a2), "r"(a3), "r"(b0), "r"(b1));
}

__device__ __forceinline__ void ldsm_x4(unsigned& a0, unsigned& a1,
                                        unsigned& a2, unsigned& a3, unsigned saddr) {
    asm volatile("ldmatrix.sync.aligned.m8n8.x4.shared.b16 {%0,%1,%2,%3}, [%4];"
                 : "=r"(a0), "=r"(a1), "=r"(a2), "=r"(a3) : "r"(saddr));
}

// Load one K-chunk of z = [x_t | h] into registers (2 float4 per thread).
__device__ __forceinline__ void ld_chunk(float4* v, const float* __restrict__ x_seq,
                                         int s, int c, int p, int b0, int tid) {
    if (s == 0 && c > 0) {   // h0 = 0
        v[0] = make_float4(0.f, 0.f, 0.f, 0.f);
        v[1] = v[0];
        return;
    }
    const float* src;
    int stride;
    if (c == 0) { src = x_seq + ((size_t)s * BATCH + b0) * DIN; stride = DIN; }
    else        { src = &g_h[p][b0][0] + (c - 1) * KC;           stride = HID; }
#pragma unroll
    for (int i = 0; i < 2; i++) {
        int f  = i * NTHREADS + tid;   // 0..1023 float4s
        int m  = f >> 5;               // row 0..31
        int k4 = (f & 31) * 4;         // 0..124
        v[i] = *(const float4*)(src + (size_t)m * stride + k4);
    }
}

// Store prefetched chunk into smem as fp16, row-major with XOR swizzle.
// Byte offset for (m, k): (m*256 + k*2) ^ ((m&7)<<4)  [XOR on the COMPLETE offset].
__device__ __forceinline__ void st_chunk(const float4* v, char* zbuf, int tid) {
#pragma unroll
    for (int i = 0; i < 2; i++) {
        int f  = i * NTHREADS + tid;
        int m  = f >> 5;
        int k4 = (f & 31) * 4;
        unsigned off = (unsigned)(m * 256 + k4 * 2) ^ (((unsigned)m & 7u) << 4);
        __half2 h01 = __float22half2_rn(make_float2(v[i].x, v[i].y));
        __half2 h23 = __float22half2_rn(make_float2(v[i].z, v[i].w));
        uint2 pk;
        pk.x = *(unsigned*)&h01;
        pk.y = *(unsigned*)&h23;
        *(uint2*)(zbuf + off) = pk;
    }
}

__global__ void __launch_bounds__(NTHREADS, 1)
liquid_kernel(const float* __restrict__ x_seq,
              const float* __restrict__ Wc, const float* __restrict__ bc,
              const float* __restrict__ Wt, const float* __restrict__ bt,
              const float* __restrict__ Wo, const float* __restrict__ bo,
              float* __restrict__ out) {
    extern __shared__ unsigned smem[];
    unsigned* sWf  = smem + OFF_WF;
    char*     sZ   = (char*)(smem + OFF_Z);
    float*    sEpi = (float*)(smem + OFF_EPI);
    float*    sBc  = (float*)(smem + OFF_BC);
    float*    sBt  = (float*)(smem + OFF_BT);

    const int tid  = threadIdx.x;
    const int gb   = blockIdx.x / P_N;
    const int jn   = blockIdx.x % P_N;
    const int b0   = gb * B_TILE;
    const int n0   = jn * N_SLICE;
    const int lane = tid & 31;
    const int wid  = tid >> 5;           // 0..15
    const int wm   = wid & 1;            // M half (16 rows)
    const int wn   = (wid >> 1) & 1;     // N half (32 combined cols)
    const int wk   = wid >> 2;           // K quarter (2 kg16 per chunk)

    // ---- init: weights into B-fragment layout (fp16) ----
    // u32 index e = ((kgg*4 + ntp)*32 + lane)*4 + q
    //   nt = 2*ntp + (q>>1), reg = q&1
    //   value = half2( W[k0][cc], W[k0+1][cc] ), k0 = kgg*16+(lane&3)*2+reg*8,
    //   cc = nt*8 + (lane>>2)
    for (int e = tid; e < KGG_TOT * 4 * 32 * 4; e += NTHREADS) {
        int q    = e & 3;
        int l    = (e >> 2) & 31;
        int ntp  = (e >> 7) & 3;
        int kgg  = e >> 9;
        int nt   = 2 * ntp + (q >> 1);
        int k0   = kgg * 16 + (l & 3) * 2 + (q & 1) * 8;
        int cc   = nt * 8 + (l >> 2);
        const float* W = (cc < N_SLICE) ? (Wc + n0 + cc) : (Wt + n0 + cc - N_SLICE);
        float w0 = W[(size_t)k0 * HID];
        float w1 = W[(size_t)(k0 + 1) * HID];
        __half2 h = __float22half2_rn(make_float2(w0, w1));
        sWf[e] = *(unsigned*)&h;
    }
    if (tid < N_SLICE) { sBc[tid] = bc[n0 + tid]; sBt[tid] = bt[n0 + tid]; }
    const float wo_v = Wo[n0 + lane];
    const float bo_v = bo[0];

    // Precompute the TWO ldmatrix addresses this warp uses (kg = wk*2 + {0,1}
    // is chunk-invariant). Swizzle XOR is applied to the COMPLETE offset
    // (row*256 + kg*32 + sel*16); only zoff (bit 13, carry-free) is added later.
    const int arow = wm * 16 + ((lane >> 3) & 1) * 8 + (lane & 7);
    const int acol = ((lane >> 4) & 1) * 16;
    const unsigned zsh = (unsigned)__cvta_generic_to_shared(sZ);
    unsigned aoff[2];
#pragma unroll
    for (int i = 0; i < 2; i++) {
        int kg = wk * 2 + i;
        aoff[i] = zsh + (((unsigned)(arow * 256 + kg * 32 + acol)) ^
                         (((unsigned)arow & 7u) << 4));
    }

    float4 vNext[2];
    ld_chunk(vNext, x_seq, 0, 0, 0, b0, tid);   // stage x chunk for step 0
    st_chunk(vNext, sZ, tid);
    __syncthreads();

    unsigned lsense = 0;

    for (int s = 0; s < T_STEPS; s++) {
        const int p = s & 1;

        // ---- finish y for previous step (warp 0) ----
        if (s > 0 && tid < 32) {
            int r = tid >> 4, j = tid & 15;
            int b = b0 + jn * 2 + r;
            float v = g_ypart[(s & 1) ^ 1][b][j];
#pragma unroll
            for (int o = 8; o; o >>= 1) v += __shfl_xor_sync(0xffffffffu, v, o);
            if (j == 0) out[(size_t)(s - 1) * BATCH + b] = v + bo_v;
        }

        // ---- GEMM: [32 x 64] = z[32 x 640] @ [Wc|Wt][640 x 64] ----
        float acc[4][4] = {};

        for (int c = 0; c < NCHUNK; c++) {
            if (c + 1 < NCHUNK) ld_chunk(vNext, x_seq, s, c + 1, p, b0, tid);

            const unsigned zoff = (unsigned)((c & 1) * ZBUF_BYTES);
#pragma unroll
            for (int i = 0; i < 2; i++) {
                int kg  = wk * 2 + i;            // kg16 within chunk (0..7)
                int kgg = c * NKG + kg;          // global kg16 (0..39)
                unsigned a0, a1, a2, a3;
                ldsm_x4(a0, a1, a2, a3, aoff[i] + zoff);
#pragma unroll
                for (int tp = 0; tp < 2; tp++) {
                    int ntp = wn * 2 + tp;
                    uint4 bf = *(const uint4*)(sWf + ((kgg * 4 + ntp) * 32 + lane) * 4);
                    mma_f16(acc[tp * 2 + 0], a0, a1, a2, a3, bf.x, bf.y);
                    mma_f16(acc[tp * 2 + 1], a0, a1, a2, a3, bf.z, bf.w);
                }
            }

            if (c + 1 < NCHUNK) st_chunk(vNext, sZ + ((c + 1) & 1) * ZBUF_BYTES, tid);
            __syncthreads();
        }

        // ---- prestage next step's x chunk (independent of h) into buf0 ----
        if (s + 1 < T_STEPS) {
            ld_chunk(vNext, x_seq, s + 1, 0, p ^ 1, b0, tid);
            st_chunk(vNext, sZ, tid);
        }

        // ---- scatter partial accumulators to per-wk epilogue buffers ----
        {
            float* eb = sEpi + wk * 2112;
            int row = wm * 16 + (lane >> 2);
#pragma unroll
            for (int t = 0; t < 4; t++) {
                int col = wn * 32 + t * 8 + (lane & 3) * 2;
                *(float2*)&eb[row * 66 + col]       = make_float2(acc[t][0], acc[t][1]);
                *(float2*)&eb[(row + 8) * 66 + col] = make_float2(acc[t][2], acc[t][3]);
            }
        }
        __syncthreads();

        // ---- elementwise: reduce wk partials, tanh/sigmoid/Euler, y-partials ----
#pragma unroll
        for (int i = 0; i < 2; i++) {
            int e  = i * NTHREADS + tid;   // 0..1023
            int b  = e >> 5;
            int nl = e & 31;               // == lane
            float h = (s == 0) ? 0.f : g_h[p][b0 + b][n0 + nl];  // issue early
            float uc = sBc[nl], ut = sBt[nl];
#pragma unroll
            for (int q = 0; q < 4; q++) {
                uc += sEpi[q * 2112 + b * 66 + nl];
                ut += sEpi[q * 2112 + b * 66 + nl + 32];
            }
            float ea   = __expf(-2.f * fabsf(uc));
            float cand = copysignf(__fdividef(1.f - ea, 1.f + ea), uc);
            float sg   = __fdividef(1.f, 1.f + __expf(-ut));
            float tau  = 0.2f + 1.8f * sg;
            float hn   = h + 0.1f * __fdividef(cand - h, tau);
            g_h[p ^ 1][b0 + b][n0 + nl] = hn;
            __stcs(&out[(size_t)T_STEPS * BATCH +
                        ((size_t)s * BATCH + b0 + b) * HID + n0 + nl], tau);

            float pp = hn * wo_v;
#pragma unroll
            for (int o = 16; o; o >>= 1) pp += __shfl_xor_sync(0xffffffffu, pp, o);
            if (lane == 0) g_ypart[s & 1][b0 + b][jn] = pp;
        }

        // ---- per-group sense-reversing barrier (16 CTAs) ----
        __threadfence();
        __syncthreads();
        if (tid == 0) {
            unsigned my = lsense ^ 1u;
            lsense = my;
            unsigned old = atomicAdd(&g_count[gb], 1u);
            if (old == P_N - 1u) {
                g_count[gb] = 0u;
                __threadfence();
                g_sense[gb] = my;
            } else {
                while (g_sense[gb] != my) { }
                __threadfence();
            }
        }
        __syncthreads();
    }

    // ---- y for the final step ----
    if (tid < 32) {
        int r = tid >> 4, j = tid & 15;
        int b = b0 + jn * 2 + r;
        float v = g_ypart[(T_STEPS & 1) ^ 1][b][j];
#pragma unroll
        for (int o = 8; o; o >>= 1) v += __shfl_xor_sync(0xffffffffu, v, o);
        if (j == 0) out[(size_t)(T_STEPS - 1) * BATCH + b] = v + bo_v;
    }
}

extern "C" void kernel_launch(void* const* d_in, const int* in_sizes, int n_in,
                              void* d_out, int out_size) {
    (void)in_sizes; (void)n_in; (void)out_size;
    const float* x_seq = (const float*)d_in[0];
    const float* Wc    = (const float*)d_in[1];
    const float* bc    = (const float*)d_in[2];
    const float* Wt    = (const float*)d_in[3];
    const float* bt    = (const float*)d_in[4];
    const float* Wo    = (const float*)d_in[5];
    const float* bo    = (const float*)d_in[6];
    float* out = (float*)d_out;

    cudaFuncSetAttribute(liquid_kernel, cudaFuncAttributeMaxDynamicSharedMemorySize, SMEM_BYTES);
    liquid_kernel<<<GRID, NTHREADS, SMEM_BYTES>>>(x_seq, Wc, bc, Wt, bt, Wo, bo, out);
}

// round 5
// speedup vs baseline: 2.8061x; 1.1826x over previous
#include <cuda_runtime.h>
#include <cuda_fp16.h>
#include <cstdint>

// Problem constants
#define T_STEPS 512
#define BATCH   256
#define DIN     128
#define HID     512
#define KTOT    640          // DIN + HID

// Tiling
#define P_B 8                // batch groups
#define P_N 16               // n-slices per group
#define B_TILE 32            // batch rows per CTA (M)
#define N_SLICE 32           // H columns per CTA
#define KC 128               // K chunk (halves) per z slot
#define NCHUNK 5             // 640 / 128
#define NKG 8                // kg16 groups per chunk
#define KGG_TOT 40           // 640 / 16
#define NTHREADS 512
#define GRID (P_B * P_N)

// Shared memory layout (uint32 units)
#define OFF_WF  0            // B frag layout: 40 kg * 4 ntp * 32 lane * 4 = 20480 u32 (80KB)
#define OFF_Z   20480        // 5 chunk slots * 2048 u32 (each 32 rows x 128 halves = 8KB)
#define OFF_EPI 30720        // 4 wk-buffers * 32*66 = 8448
#define OFF_BC  39168        // 32
#define OFF_BT  39200        // 32
#define SMEM_U32 39232
#define SMEM_BYTES (SMEM_U32 * 4)   // 156928 B

#define ZBUF_BYTES 8192

// Persistent device state
__device__ float    g_h[2][BATCH][HID];
__device__ float    g_ypart[2][BATCH][P_N];
__device__ unsigned g_count[P_B];
__device__ unsigned g_sense[P_B];   // 512 toggles/launch -> returns to 0 (graph-replay safe)

__device__ __forceinline__ void mma_f16(float* c, unsigned a0, unsigned a1,
                                        unsigned a2, unsigned a3,
                                        unsigned b0, unsigned b1) {
    asm("mma.sync.aligned.m16n8k16.row.col.f32.f16.f16.f32 "
        "{%0,%1,%2,%3},{%4,%5,%6,%7},{%8,%9},{%0,%1,%2,%3};"
        : "+f"(c[0]), "+f"(c[1]), "+f"(c[2]), "+f"(c[3])
        : "r"(a0), "r"(a1), "r"(a2), "r"(a3), "r"(b0), "r"(b1));
}

__device__ __forceinline__ void ldsm_x4(unsigned& a0, unsigned& a1,
                                        unsigned& a2, unsigned& a3, unsigned saddr) {
    asm volatile("ldmatrix.sync.aligned.m8n8.x4.shared.b16 {%0,%1,%2,%3}, [%4];"
                 : "=r"(a0), "=r"(a1), "=r"(a2), "=r"(a3) : "r"(saddr));
}

// Store one staged chunk into smem as fp16, row-major, XOR swizzle on the
// COMPLETE byte offset: (m*256 + k*2) ^ ((m&7)<<4).
__device__ __forceinline__ void st_chunk(const float4* v, char* zbuf, int tid) {
#pragma unroll
    for (int i = 0; i < 2; i++) {
        int f  = i * NTHREADS + tid;
        int m  = f >> 5;
        int k4 = (f & 31) * 4;
        unsigned off = (unsigned)(m * 256 + k4 * 2) ^ (((unsigned)m & 7u) << 4);
        __half2 h01 = __float22half2_rn(make_float2(v[i].x, v[i].y));
        __half2 h23 = __float22half2_rn(make_float2(v[i].z, v[i].w));
        uint2 pk;
        pk.x = *(unsigned*)&h01;
        pk.y = *(unsigned*)&h23;
        *(uint2*)(zbuf + off) = pk;
    }
}

__global__ void __launch_bounds__(NTHREADS, 1)
liquid_kernel(const float* __restrict__ x_seq,
              const float* __restrict__ Wc, const float* __restrict__ bc,
              const float* __restrict__ Wt, const float* __restrict__ bt,
              const float* __restrict__ Wo, const float* __restrict__ bo,
              float* __restrict__ out) {
    extern __shared__ unsigned smem[];
    unsigned* sWf  = smem + OFF_WF;
    char*     sZ   = (char*)(smem + OFF_Z);
    float*    sEpi = (float*)(smem + OFF_EPI);
    float*    sBc  = (float*)(smem + OFF_BC);
    float*    sBt  = (float*)(smem + OFF_BT);

    const int tid  = threadIdx.x;
    const int gb   = blockIdx.x / P_N;
    const int jn   = blockIdx.x % P_N;
    const int b0   = gb * B_TILE;
    const int n0   = jn * N_SLICE;
    const int lane = tid & 31;
    const int wid  = tid >> 5;           // 0..15
    const int wm   = wid & 1;            // M half (16 rows)
    const int wn   = (wid >> 1) & 1;     // N half (32 combined cols)
    const int wk   = wid >> 2;           // K quarter (2 kg16 per chunk)

    // ---- init: weights into B-fragment layout (fp16) ----
    for (int e = tid; e < KGG_TOT * 4 * 32 * 4; e += NTHREADS) {
        int q    = e & 3;
        int l    = (e >> 2) & 31;
        int ntp  = (e >> 7) & 3;
        int kgg  = e >> 9;
        int nt   = 2 * ntp + (q >> 1);
        int k0   = kgg * 16 + (l & 3) * 2 + (q & 1) * 8;
        int cc   = nt * 8 + (l >> 2);
        const float* W = (cc < N_SLICE) ? (Wc + n0 + cc) : (Wt + n0 + cc - N_SLICE);
        float w0 = W[(size_t)k0 * HID];
        float w1 = W[(size_t)(k0 + 1) * HID];
        __half2 h = __float22half2_rn(make_float2(w0, w1));
        sWf[e] = *(unsigned*)&h;
    }
    if (tid < N_SLICE) { sBc[tid] = bc[n0 + tid]; sBt[tid] = bt[n0 + tid]; }
    const float wo_v = Wo[n0 + lane];
    const float bo_v = bo[0];

    // Per-thread staging coordinates (step-invariant)
    const int sm0 = tid >> 5;                 // row for i=0
    const int sk0 = (tid & 31) * 4;           // k4 for both i
    const int sm1 = (NTHREADS + tid) >> 5;    // row for i=1

    // Precompute the TWO ldmatrix base offsets (kg = wk*2 + {0,1}); swizzle
    // applied to the complete low-13-bit offset; chunk slot adds bits 13+.
    const int arow = wm * 16 + ((lane >> 3) & 1) * 8 + (lane & 7);
    const int acol = ((lane >> 4) & 1) * 16;
    const unsigned zsh = (unsigned)__cvta_generic_to_shared(sZ);
    unsigned aoff[2];
#pragma unroll
    for (int i = 0; i < 2; i++) {
        int kg = wk * 2 + i;
        aoff[i] = zsh + (((unsigned)(arow * 256 + kg * 32 + acol)) ^
                         (((unsigned)arow & 7u) << 4));
    }

    // Register-resident h for this thread's two epilogue elements
    float h_loc[2] = {0.f, 0.f};

    // Prestage x chunk for step 0 into slot 0
    {
        float4 vx[2];
        const float* src = x_seq + (size_t)b0 * DIN;
        vx[0] = *(const float4*)(src + (size_t)sm0 * DIN + sk0);
        vx[1] = *(const float4*)(src + (size_t)sm1 * DIN + sk0);
        st_chunk(vx, sZ, tid);
    }
    __syncthreads();

    unsigned lsense = 0;

    for (int s = 0; s < T_STEPS; s++) {
        const int p = s & 1;

        // ---- stage h chunks 1..4 (one LDG burst, L2-direct) ----
        float4 hv[4][2];
        if (s > 0) {
            const float* hb = &g_h[p][b0][0];
#pragma unroll
            for (int c = 0; c < 4; c++) {
                const float* src = hb + c * KC;
                hv[c][0] = __ldcg((const float4*)(src + (size_t)sm0 * HID + sk0));
                hv[c][1] = __ldcg((const float4*)(src + (size_t)sm1 * HID + sk0));
            }
        } else {
#pragma unroll
            for (int c = 0; c < 4; c++) {
                hv[c][0] = make_float4(0.f, 0.f, 0.f, 0.f);
                hv[c][1] = hv[c][0];
            }
        }
#pragma unroll
        for (int c = 0; c < 4; c++)
            st_chunk(hv[c], sZ + (c + 1) * ZBUF_BYTES, tid);

        // ---- finish y for previous step (warp 0) while others stage ----
        if (s > 0 && tid < 32) {
            int r = tid >> 4, j = tid & 15;
            int b = b0 + jn * 2 + r;
            float v = __ldcg(&g_ypart[p ^ 1][b][j]);
#pragma unroll
            for (int o = 8; o; o >>= 1) v += __shfl_xor_sync(0xffffffffu, v, o);
            if (j == 0) out[(size_t)(s - 1) * BATCH + b] = v + bo_v;
        }
        __syncthreads();

        // ---- issue next step's x-chunk LDG (hidden under MMA) ----
        float4 vx[2];
        if (s + 1 < T_STEPS) {
            const float* src = x_seq + ((size_t)(s + 1) * BATCH + b0) * DIN;
            vx[0] = *(const float4*)(src + (size_t)sm0 * DIN + sk0);
            vx[1] = *(const float4*)(src + (size_t)sm1 * DIN + sk0);
        }

        // ---- GEMM: [32 x 64] = z[32 x 640] @ [Wc|Wt][640 x 64] ----
        float acc[4][4] = {};
#pragma unroll
        for (int c = 0; c < NCHUNK; c++) {
            const unsigned zoff = (unsigned)(c * ZBUF_BYTES);
#pragma unroll
            for (int i = 0; i < 2; i++) {
                int kgg = c * NKG + wk * 2 + i;
                unsigned a0, a1, a2, a3;
                ldsm_x4(a0, a1, a2, a3, aoff[i] + zoff);
#pragma unroll
                for (int tp = 0; tp < 2; tp++) {
                    int ntp = wn * 2 + tp;
                    uint4 bf = *(const uint4*)(sWf + ((kgg * 4 + ntp) * 32 + lane) * 4);
                    mma_f16(acc[tp * 2 + 0], a0, a1, a2, a3, bf.x, bf.y);
                    mma_f16(acc[tp * 2 + 1], a0, a1, a2, a3, bf.z, bf.w);
                }
            }
        }

        // ---- scatter partial accumulators to per-wk epilogue buffers ----
        {
            float* eb = sEpi + wk * 2112;
            int row = wm * 16 + (lane >> 2);
#pragma unroll
            for (int t = 0; t < 4; t++) {
                int col = wn * 32 + t * 8 + (lane & 3) * 2;
                *(float2*)&eb[row * 66 + col]       = make_float2(acc[t][0], acc[t][1]);
                *(float2*)&eb[(row + 8) * 66 + col] = make_float2(acc[t][2], acc[t][3]);
            }
        }
        __syncthreads();

        // ---- prestage next x into slot 0 (all MMA reads done) ----
        if (s + 1 < T_STEPS) st_chunk(vx, sZ, tid);

        // ---- elementwise: reduce wk partials, tanh/sigmoid/Euler, y-partials ----
#pragma unroll
        for (int i = 0; i < 2; i++) {
            int e  = i * NTHREADS + tid;   // 0..1023
            int b  = e >> 5;
            int nl = e & 31;               // == lane
            float uc = sBc[nl], ut = sBt[nl];
#pragma unroll
            for (int q = 0; q < 4; q++) {
                uc += sEpi[q * 2112 + b * 66 + nl];
                ut += sEpi[q * 2112 + b * 66 + nl + 32];
            }
            float ea   = __expf(-2.f * fabsf(uc));
            float cand = copysignf(__fdividef(1.f - ea, 1.f + ea), uc);
            float sg   = __fdividef(1.f, 1.f + __expf(-ut));
            float tau  = 0.2f + 1.8f * sg;
            float h    = h_loc[i];
            float hn   = h + 0.1f * __fdividef(cand - h, tau);
            h_loc[i]   = hn;
            g_h[p ^ 1][b0 + b][n0 + nl] = hn;
            __stcs(&out[(size_t)T_STEPS * BATCH +
                        ((size_t)s * BATCH + b0 + b) * HID + n0 + nl], tau);

            float pp = hn * wo_v;
#pragma unroll
            for (int o = 16; o; o >>= 1) pp += __shfl_xor_sync(0xffffffffu, pp, o);
            if (lane == 0) g_ypart[s & 1][b0 + b][jn] = pp;
        }

        // ---- per-group release/acquire barrier (16 CTAs, no L1 flush) ----
        __syncthreads();
        if (tid == 0) {
            lsense ^= 1u;
            unsigned old;
            asm volatile("atom.add.release.gpu.global.u32 %0, [%1], %2;"
                         : "=r"(old) : "l"(&g_count[gb]), "r"(1u) : "memory");
            if (old == P_N - 1u) {
                g_count[gb] = 0u;
                asm volatile("st.release.gpu.global.u32 [%0], %1;"
                             :: "l"(&g_sense[gb]), "r"(lsense) : "memory");
            } else {
                unsigned v;
                do {
                    asm volatile("ld.acquire.gpu.global.u32 %0, [%1];"
                                 : "=r"(v) : "l"(&g_sense[gb]) : "memory");
                } while (v != lsense);
            }
        }
        __syncthreads();
    }

    // ---- y for the final step ----
    if (tid < 32) {
        int r = tid >> 4, j = tid & 15;
        int b = b0 + jn * 2 + r;
        float v = __ldcg(&g_ypart[(T_STEPS & 1) ^ 1][b][j]);
#pragma unroll
        for (int o = 8; o; o >>= 1) v += __shfl_xor_sync(0xffffffffu, v, o);
        if (j == 0) out[(size_t)(T_STEPS - 1) * BATCH + b] = v + bo_v;
    }
}

extern "C" void kernel_launch(void* const* d_in, const int* in_sizes, int n_in,
                              void* d_out, int out_size) {
    (void)in_sizes; (void)n_in; (void)out_size;
    const float* x_seq = (const float*)d_in[0];
    const float* Wc    = (const float*)d_in[1];
    const float* bc    = (const float*)d_in[2];
    const float* Wt    = (const float*)d_in[3];
    const float* bt    = (const float*)d_in[4];
    const float* Wo    = (const float*)d_in[5];
    const float* bo    = (const float*)d_in[6];
    float* out = (float*)d_out;

    cudaFuncSetAttribute(liquid_kernel, cudaFuncAttributeMaxDynamicSharedMemorySize, SMEM_BYTES);
    liquid_kernel<<<GRID, NTHREADS, SMEM_BYTES>>>(x_seq, Wc, bc, Wt, bt, Wo, bo, out);
}

// round 6
// speedup vs baseline: 2.8411x; 1.0125x over previous
#include <cuda_runtime.h>
#include <cuda_fp16.h>
#include <cstdint>

// Problem constants
#define T_STEPS 512
#define BATCH   256
#define DIN     128
#define HID     512
#define KTOT    640          // DIN + HID

// Tiling
#define P_B 8                // batch groups
#define P_N 16               // n-slices per group
#define B_TILE 32            // batch rows per CTA (M)
#define N_SLICE 32           // H columns per CTA
#define KC 128               // K chunk (halves) per z slot
#define NCHUNK 5             // 640 / 128
#define NKG 8                // kg16 groups per chunk
#define KGG_TOT 40           // 640 / 16
#define NTHREADS 512
#define GRID (P_B * P_N)

// Shared memory layout (uint32 units)
#define OFF_WF  0            // B frag layout: 40 kg * 4 ntp * 32 lane * 4 = 20480 u32 (80KB)
#define OFF_Z   20480        // 5 chunk slots * 2048 u32 (each 32 rows x 128 halves = 8KB)
#define OFF_EPI 30720        // 4 wk-buffers * 32*66 = 8448
#define OFF_BC  39168        // 32
#define OFF_BT  39200        // 32
#define SMEM_U32 39232
#define SMEM_BYTES (SMEM_U32 * 4)   // 156928 B

#define ZBUF_BYTES 8192

// Persistent device state.
// g_hz: hidden state as fp16, PRE-SWIZZLED in the smem fragment byte layout.
// Chunk slot c (0..3) holds h columns [c*128, c*128+128); byte offset within a
// chunk for (m, k') is (m*256 + k'*2) ^ ((m&7)<<4). Staging = identity copy.
__device__ __align__(16) char g_hz[2][P_B][4][ZBUF_BYTES];
__device__ float    g_ypart[2][BATCH][P_N];
__device__ unsigned g_count[P_B];
__device__ unsigned g_sense[P_B];   // 512 toggles/launch -> returns to 0 (graph-replay safe)

__device__ __forceinline__ void mma_f16(float* c, unsigned a0, unsigned a1,
                                        unsigned a2, unsigned a3,
                                        unsigned b0, unsigned b1) {
    asm("mma.sync.aligned.m16n8k16.row.col.f32.f16.f16.f32 "
        "{%0,%1,%2,%3},{%4,%5,%6,%7},{%8,%9},{%0,%1,%2,%3};"
        : "+f"(c[0]), "+f"(c[1]), "+f"(c[2]), "+f"(c[3])
        : "r"(a0), "r"(a1), "r"(a2), "r"(a3), "r"(b0), "r"(b1));
}

__device__ __forceinline__ void ldsm_x4(unsigned& a0, unsigned& a1,
                                        unsigned& a2, unsigned& a3, unsigned saddr) {
    asm volatile("ldmatrix.sync.aligned.m8n8.x4.shared.b16 {%0,%1,%2,%3}, [%4];"
                 : "=r"(a0), "=r"(a1), "=r"(a2), "=r"(a3) : "r"(saddr));
}

// Store one fp32 chunk into smem as fp16, XOR swizzle on the COMPLETE byte
// offset: (m*256 + k*2) ^ ((m&7)<<4). Used only for the x chunk (slot 0).
__device__ __forceinline__ void st_chunk(const float4* v, char* zbuf, int tid) {
#pragma unroll
    for (int i = 0; i < 2; i++) {
        int f  = i * NTHREADS + tid;
        int m  = f >> 5;
        int k4 = (f & 31) * 4;
        unsigned off = (unsigned)(m * 256 + k4 * 2) ^ (((unsigned)m & 7u) << 4);
        __half2 h01 = __float22half2_rn(make_float2(v[i].x, v[i].y));
        __half2 h23 = __float22half2_rn(make_float2(v[i].z, v[i].w));
        uint2 pk;
        pk.x = *(unsigned*)&h01;
        pk.y = *(unsigned*)&h23;
        *(uint2*)(zbuf + off) = pk;
    }
}

__global__ void __launch_bounds__(NTHREADS, 1)
liquid_kernel(const float* __restrict__ x_seq,
              const float* __restrict__ Wc, const float* __restrict__ bc,
              const float* __restrict__ Wt, const float* __restrict__ bt,
              const float* __restrict__ Wo, const float* __restrict__ bo,
              float* __restrict__ out) {
    extern __shared__ unsigned smem[];
    unsigned* sWf  = smem + OFF_WF;
    char*     sZ   = (char*)(smem + OFF_Z);
    float*    sEpi = (float*)(smem + OFF_EPI);
    float*    sBc  = (float*)(smem + OFF_BC);
    float*    sBt  = (float*)(smem + OFF_BT);

    const int tid  = threadIdx.x;
    const int gb   = blockIdx.x / P_N;
    const int jn   = blockIdx.x % P_N;
    const int b0   = gb * B_TILE;
    const int n0   = jn * N_SLICE;
    const int lane = tid & 31;
    const int wid  = tid >> 5;           // 0..15
    const int wm   = wid & 1;            // M half (16 rows)
    const int wn   = (wid >> 1) & 1;     // N half (32 combined cols)
    const int wk   = wid >> 2;           // K quarter (2 kg16 per chunk)

    // ---- init: weights into B-fragment layout (fp16) ----
    for (int e = tid; e < KGG_TOT * 4 * 32 * 4; e += NTHREADS) {
        int q    = e & 3;
        int l    = (e >> 2) & 31;
        int ntp  = (e >> 7) & 3;
        int kgg  = e >> 9;
        int nt   = 2 * ntp + (q >> 1);
        int k0   = kgg * 16 + (l & 3) * 2 + (q & 1) * 8;
        int cc   = nt * 8 + (l >> 2);
        const float* W = (cc < N_SLICE) ? (Wc + n0 + cc) : (Wt + n0 + cc - N_SLICE);
        float w0 = W[(size_t)k0 * HID];
        float w1 = W[(size_t)(k0 + 1) * HID];
        __half2 h = __float22half2_rn(make_float2(w0, w1));
        sWf[e] = *(unsigned*)&h;
    }
    if (tid < N_SLICE) { sBc[tid] = bc[n0 + tid]; sBt[tid] = bt[n0 + tid]; }
    const float wo_v = Wo[n0 + lane];
    const float bo_v = bo[0];

    // Per-thread staging coordinates for the x chunk (step-invariant)
    const int sm0 = tid >> 5;
    const int sk0 = (tid & 31) * 4;
    const int sm1 = (NTHREADS + tid) >> 5;

    // Precompute the TWO ldmatrix base offsets (kg = wk*2 + {0,1}); swizzle
    // applied to the complete low-13-bit offset; chunk slot adds bits 13+.
    const int arow = wm * 16 + ((lane >> 3) & 1) * 8 + (lane & 7);
    const int acol = ((lane >> 4) & 1) * 16;
    const unsigned zsh = (unsigned)__cvta_generic_to_shared(sZ);
    unsigned aoff[2];
#pragma unroll
    for (int i = 0; i < 2; i++) {
        int kg = wk * 2 + i;
        aoff[i] = zsh + (((unsigned)(arow * 256 + kg * 32 + acol)) ^
                         (((unsigned)arow & 7u) << 4));
    }

    // Epilogue element coordinates (2 per thread, step-invariant):
    // element i: b = i*16 + wid, nl = lane, hcol = n0 + nl
    const int hcol   = n0 + lane;
    char* const hz_w0 = &g_hz[0][gb][hcol >> 7]
        [((unsigned)((wid) * 256 + (hcol & 127) * 2)) ^ (((unsigned)wid & 7u) << 4)];
    char* const hz_w1 = &g_hz[0][gb][hcol >> 7]
        [((unsigned)((16 + wid) * 256 + (hcol & 127) * 2)) ^ (((unsigned)(16 + wid) & 7u) << 4)];
    const size_t hz_buf_stride = (size_t)P_B * 4 * ZBUF_BYTES;   // g_hz[1] - g_hz[0]

    float h_loc[2] = {0.f, 0.f};

    // Prestage x chunk for step 0 into slot 0
    {
        float4 vx[2];
        const float* src = x_seq + (size_t)b0 * DIN;
        vx[0] = *(const float4*)(src + (size_t)sm0 * DIN + sk0);
        vx[1] = *(const float4*)(src + (size_t)sm1 * DIN + sk0);
        st_chunk(vx, sZ, tid);
    }
    __syncthreads();

    unsigned lsense = 0;

    for (int s = 0; s < T_STEPS; s++) {
        const int p = s & 1;

        // ---- stage h chunks 1..4: identity copy of pre-swizzled fp16 ----
        if (s > 0) {
            const char* hb = &g_hz[p][gb][0][0];
#pragma unroll
            for (int c = 0; c < 4; c++) {
                uint4 v = __ldcg((const uint4*)(hb + c * ZBUF_BYTES) + tid);
                *((uint4*)(sZ + (c + 1) * ZBUF_BYTES) + tid) = v;
            }
        } else {
            uint4 z = make_uint4(0u, 0u, 0u, 0u);
#pragma unroll
            for (int c = 0; c < 4; c++)
                *((uint4*)(sZ + (c + 1) * ZBUF_BYTES) + tid) = z;
        }

        // ---- finish y for previous step (2 batch rows per CTA) ----
        if (s > 0 && tid < 32) {
            int r = tid >> 4, j = tid & 15;
            int b = b0 + jn * 2 + r;
            float v = __ldcg(&g_ypart[p ^ 1][b][j]);
#pragma unroll
            for (int o = 8; o; o >>= 1) v += __shfl_xor_sync(0xffffffffu, v, o);
            if (j == 0) out[(size_t)(s - 1) * BATCH + b] = v + bo_v;
        }
        __syncthreads();

        // ---- issue next step's x-chunk LDG (hidden under MMA) ----
        float4 vx[2];
        if (s + 1 < T_STEPS) {
            const float* src = x_seq + ((size_t)(s + 1) * BATCH + b0) * DIN;
            vx[0] = *(const float4*)(src + (size_t)sm0 * DIN + sk0);
            vx[1] = *(const float4*)(src + (size_t)sm1 * DIN + sk0);
        }

        // ---- GEMM: [32 x 64] = z[32 x 640] @ [Wc|Wt][640 x 64] ----
        float acc[4][4] = {};
#pragma unroll
        for (int c = 0; c < NCHUNK; c++) {
            const unsigned zoff = (unsigned)(c * ZBUF_BYTES);
#pragma unroll
            for (int i = 0; i < 2; i++) {
                int kgg = c * NKG + wk * 2 + i;
                unsigned a0, a1, a2, a3;
                ldsm_x4(a0, a1, a2, a3, aoff[i] + zoff);
#pragma unroll
                for (int tp = 0; tp < 2; tp++) {
                    int ntp = wn * 2 + tp;
                    uint4 bf = *(const uint4*)(sWf + ((kgg * 4 + ntp) * 32 + lane) * 4);
                    mma_f16(acc[tp * 2 + 0], a0, a1, a2, a3, bf.x, bf.y);
                    mma_f16(acc[tp * 2 + 1], a0, a1, a2, a3, bf.z, bf.w);
                }
            }
        }

        // ---- scatter partial accumulators to per-wk epilogue buffers ----
        {
            float* eb = sEpi + wk * 2112;
            int row = wm * 16 + (lane >> 2);
#pragma unroll
            for (int t = 0; t < 4; t++) {
                int col = wn * 32 + t * 8 + (lane & 3) * 2;
                *(float2*)&eb[row * 66 + col]       = make_float2(acc[t][0], acc[t][1]);
                *(float2*)&eb[(row + 8) * 66 + col] = make_float2(acc[t][2], acc[t][3]);
            }
        }
        __syncthreads();

        // ---- epilogue (pre-barrier part): reduce, activations, h update ----
        float tau_sv[2];
        char* hz_base0 = hz_w0 + (size_t)(p ^ 1) * hz_buf_stride;
        char* hz_base1 = hz_w1 + (size_t)(p ^ 1) * hz_buf_stride;
#pragma unroll
        for (int i = 0; i < 2; i++) {
            int b  = i * 16 + wid;      // local batch row
            int nl = lane;
            float uc = sBc[nl], ut = sBt[nl];
#pragma unroll
            for (int q = 0; q < 4; q++) {
                uc += sEpi[q * 2112 + b * 66 + nl];
                ut += sEpi[q * 2112 + b * 66 + nl + 32];
            }
            float ea   = __expf(-2.f * fabsf(uc));
            float cand = copysignf(__fdividef(1.f - ea, 1.f + ea), uc);
            float sg   = __fdividef(1.f, 1.f + __expf(-ut));
            float tau  = 0.2f + 1.8f * sg;
            tau_sv[i]  = tau;
            float h    = h_loc[i];
            float hn   = h + 0.1f * __fdividef(cand - h, tau);
            h_loc[i]   = hn;
            *(__half*)(i == 0 ? hz_base0 : hz_base1) = __float2half_rn(hn);

            float pp = hn * wo_v;
#pragma unroll
            for (int o = 16; o; o >>= 1) pp += __shfl_xor_sync(0xffffffffu, pp, o);
            if (lane == 0) g_ypart[s & 1][b0 + b][jn] = pp;
        }

        // ---- barrier arrive; overlap tau stores + x staging with the spin ----
        __syncthreads();
        if (tid == 0) {
            lsense ^= 1u;
            unsigned old;
            asm volatile("atom.add.release.gpu.global.u32 %0, [%1], %2;"
                         : "=r"(old) : "l"(&g_count[gb]), "r"(1u) : "memory");
            if (old == P_N - 1u) {
                g_count[gb] = 0u;
                asm volatile("st.release.gpu.global.u32 [%0], %1;"
                             :: "l"(&g_sense[gb]), "r"(lsense) : "memory");
            } else {
                unsigned v;
                do {
                    asm volatile("ld.acquire.gpu.global.u32 %0, [%1];"
                                 : "=r"(v) : "l"(&g_sense[gb]) : "memory");
                } while (v != lsense);
            }
        }
        // tau is never read cross-CTA: store it outside the ordered region.
#pragma unroll
        for (int i = 0; i < 2; i++) {
            int b = i * 16 + wid;
            __stcs(&out[(size_t)T_STEPS * BATCH +
                        ((size_t)s * BATCH + b0 + b) * HID + n0 + lane], tau_sv[i]);
        }
        if (s + 1 < T_STEPS) st_chunk(vx, sZ, tid);   // slot 0: next x
        __syncthreads();
    }

    // ---- y for the final step ----
    if (tid < 32) {
        int r = tid >> 4, j = tid & 15;
        int b = b0 + jn * 2 + r;
        float v = __ldcg(&g_ypart[(T_STEPS & 1) ^ 1][b][j]);
#pragma unroll
        for (int o = 8; o; o >>= 1) v += __shfl_xor_sync(0xffffffffu, v, o);
        if (j == 0) out[(size_t)(T_STEPS - 1) * BATCH + b] = v + bo_v;
    }
}

extern "C" void kernel_launch(void* const* d_in, const int* in_sizes, int n_in,
                              void* d_out, int out_size) {
    (void)in_sizes; (void)n_in; (void)out_size;
    const float* x_seq = (const float*)d_in[0];
    const float* Wc    = (const float*)d_in[1];
    const float* bc    = (const float*)d_in[2];
    const float* Wt    = (const float*)d_in[3];
    const float* bt    = (const float*)d_in[4];
    const float* Wo    = (const float*)d_in[5];
    const float* bo    = (const float*)d_in[6];
    float* out = (float*)d_out;

    cudaFuncSetAttribute(liquid_kernel, cudaFuncAttributeMaxDynamicSharedMemorySize, SMEM_BYTES);
    liquid_kernel<<<GRID, NTHREADS, SMEM_BYTES>>>(x_seq, Wc, bc, Wt, bt, Wo, bo, out);
}